// round 11
// baseline (speedup 1.0000x reference)
#include <cuda_runtime.h>
#include <cuda_fp16.h>
#include <cstdint>

#define N_TOK 2048
#define B_SZ  8
#define E_DIM 256
#define H_DIM 512

// ---------------------------------------------------------------------------
// Scratch (static device globals — no runtime allocation).
// ---------------------------------------------------------------------------
__device__ __half g_x[(size_t)B_SZ * N_TOK * E_DIM];    // xn fp16 (B,N,E)
__device__ __half g_hth[(size_t)B_SZ * H_DIM * N_TOK];  // h^T fp16 (B,H,N)
__device__ __half g_P[(size_t)B_SZ * N_TOK * N_TOK];    // exp(scores) fp16
__device__ float g_rowsum[B_SZ * N_TOK];
__device__ float g_sumsq[1];

// ---------------------------------------------------------------------------
// Helpers (plain sm_103-compatible PTX: ldmatrix / mma.sync / cp.async)
// ---------------------------------------------------------------------------
__device__ __forceinline__ uint32_t smem_u32(const void* p) {
    uint32_t a;
    asm("{ .reg .u64 t; cvta.to.shared.u64 t, %1; cvt.u32.u64 %0, t; }" : "=r"(a) : "l"(p));
    return a;
}
__device__ __forceinline__ void cpa16(uint32_t dst, const void* src) {
    asm volatile("cp.async.cg.shared.global [%0], [%1], 16;"
                 :: "r"(dst), "l"(__cvta_generic_to_global(src)));
}
#define CP_COMMIT() asm volatile("cp.async.commit_group;" ::: "memory")
#define CP_WAIT(n)  asm volatile("cp.async.wait_group %0;" :: "n"(n) : "memory")

#define LDSM4(r0, r1, r2, r3, addr) \
    asm volatile("ldmatrix.sync.aligned.m8n8.x4.shared.b16 {%0,%1,%2,%3}, [%4];" \
                 : "=r"(r0), "=r"(r1), "=r"(r2), "=r"(r3) : "r"(addr))

#define MMA(c, a, b0, b1) \
    asm volatile("mma.sync.aligned.m16n8k16.row.col.f32.f16.f16.f32 " \
                 "{%0,%1,%2,%3},{%4,%5,%6,%7},{%8,%9},{%0,%1,%2,%3};" \
                 : "+f"((c)[0]), "+f"((c)[1]), "+f"((c)[2]), "+f"((c)[3]) \
                 : "r"((a)[0]), "r"((a)[1]), "r"((a)[2]), "r"((a)[3]), "r"(b0), "r"(b1))

// SW128 swizzle: 128-byte rows, xor bits[6:4] ^= bits[9:7]
#define SW(o) ((o) ^ (((o) >> 3) & 0x70u))

// per-lane ldmatrix row offsets (128-byte tile rows)
__device__ __forceinline__ uint32_t a_row_off(int mbase, int lane) {
    int row = mbase + (lane & 7) + ((lane >> 3) & 1) * 8;
    return (uint32_t)(row * 128 + (lane >> 4) * 16);
}
__device__ __forceinline__ uint32_t b_row_off(int nbase, int lane) {
    int row = nbase + (lane & 7) + ((lane >> 4) << 3);
    return (uint32_t)(row * 128 + ((lane >> 3) & 1) * 16);
}

#define STAGE_BYTES 32768
#define GEMM_SMEM (1024 + 2 * STAGE_BYTES)

// ---------------------------------------------------------------------------
// 64x64 warp-tile compute for one K=64 chunk (4 k16 steps).
// B fragments held across mi; A fragment reloaded per mi (keeps regs ~160).
// ---------------------------------------------------------------------------
__device__ __forceinline__ void compute_chunk(uint32_t aB, uint32_t bB,
                                              uint32_t aRow, uint32_t bRow,
                                              float acc[4][8][4]) {
#pragma unroll
    for (int k16 = 0; k16 < 4; k16++) {
        uint32_t aoff = SW(aRow + k16 * 32);
        uint32_t boff = SW(bRow + k16 * 32);
        uint32_t bf[4][4];
#pragma unroll
        for (int g = 0; g < 4; g++)
            LDSM4(bf[g][0], bf[g][1], bf[g][2], bf[g][3], bB + boff + g * 2048);
#pragma unroll
        for (int mi = 0; mi < 4; mi++) {
            uint32_t af[4];
            LDSM4(af[0], af[1], af[2], af[3], aB + aoff + mi * 2048);
#pragma unroll
            for (int ni = 0; ni < 8; ni++) {
                const int g = ni >> 1, p = (ni & 1) * 2;
                MMA(acc[mi][ni], af, bf[g][p], bf[g][p + 1]);
            }
        }
    }
}

// ---------------------------------------------------------------------------
// Kernel 1: row-normalize x (N,B,E) -> fp16 (B,N,E); zero accumulators.
// ---------------------------------------------------------------------------
__global__ __launch_bounds__(256) void k_normalize(const float* __restrict__ x) {
    if (blockIdx.x == 0) {
        for (int i = threadIdx.x; i < B_SZ * N_TOK; i += blockDim.x) g_rowsum[i] = 0.f;
        if (threadIdx.x == 0) g_sumsq[0] = 0.f;
    }
    int warp = (blockIdx.x * blockDim.x + threadIdx.x) >> 5;
    int lane = threadIdx.x & 31;
    if (warp >= B_SZ * N_TOK) return;
    int b = warp / N_TOK, i = warp % N_TOK;

    const float4* row = (const float4*)(x + ((size_t)i * B_SZ + b) * E_DIM);
    float4 v0 = row[lane], v1 = row[lane + 32];
    float ss = v0.x*v0.x + v0.y*v0.y + v0.z*v0.z + v0.w*v0.w
             + v1.x*v1.x + v1.y*v1.y + v1.z*v1.z + v1.w*v1.w;
#pragma unroll
    for (int o = 16; o; o >>= 1) ss += __shfl_xor_sync(0xffffffffu, ss, o);
    float r = rsqrtf(ss);

    size_t base = ((size_t)b * N_TOK + i) * E_DIM;
    float v[8] = {v0.x*r, v0.y*r, v0.z*r, v0.w*r, v1.x*r, v1.y*r, v1.z*r, v1.w*r};
#pragma unroll
    for (int half = 0; half < 2; half++) {
        int col = half * 128 + lane * 4;
        union { __half h4[4]; uint2 u; } uu;
#pragma unroll
        for (int k = 0; k < 4; k++) uu.h4[k] = __float2half_rn(v[half*4+k]);
        *(uint2*)(g_x + base + col) = uu.u;
    }
}

// ---------------------------------------------------------------------------
// Kernel 1b: transpose h (N,B,H) -> (B,H,N) fp16.
// ---------------------------------------------------------------------------
__global__ void k_ht(const float* __restrict__ h) {
    __shared__ float t[32][33];
    int b = blockIdx.z, tok0 = blockIdx.x * 32, hc0 = blockIdx.y * 32;
    int tx = threadIdx.x, ty = threadIdx.y;
#pragma unroll
    for (int k = 0; k < 4; k++)
        t[ty + 8*k][tx] = h[(size_t)(tok0 + ty + 8*k) * (B_SZ*H_DIM) + b*H_DIM + hc0 + tx];
    __syncthreads();
#pragma unroll
    for (int k = 0; k < 4; k++) {
        int r = ty + 8*k;
        g_hth[((size_t)b * H_DIM + hc0 + r) * N_TOK + tok0 + tx] = __float2half_rn(t[tx][r]);
    }
}

// ---------------------------------------------------------------------------
// Kernel 2: QK, symmetric, 4 warps (2x2 of 64x64). Lower-triangle blocks.
// ---------------------------------------------------------------------------
__global__ __launch_bounds__(128, 2) void k_qk() {
    extern __shared__ char smem_raw[];
    uint32_t sb0 = smem_u32(smem_raw);
    uint32_t sb = (sb0 + 1023) & ~1023u;
    char* sbase = smem_raw + (sb - sb0);
    const int tid = threadIdx.x, lane = tid & 31, w = tid >> 5;
    const int b = blockIdx.z;

    // decode lower-triangle block (i, j), j <= i
    int bx = blockIdx.x;
    int i = (int)((sqrtf(8.0f * bx + 1.0f) - 1.0f) * 0.5f);
    while ((i + 1) * (i + 2) / 2 <= bx) i++;
    while (i * (i + 1) / 2 > bx) i--;
    int j = bx - i * (i + 1) / 2;
    const int row0 = i * 128, col0 = j * 128;

    const __half* A = g_x + ((size_t)b * N_TOK + row0) * E_DIM;
    const __half* B = g_x + ((size_t)b * N_TOK + col0) * E_DIM;

    const int mbase = (w & 1) * 64, nbase = (w >> 1) * 64;
    const uint32_t aRow = a_row_off(mbase, lane);
    const uint32_t bRow = b_row_off(nbase, lane);
    float acc[4][8][4] = {};

    auto load = [&](int c) {
        uint32_t base = sb + (c & 1) * STAGE_BYTES;
        int k0 = c * 64;
#pragma unroll
        for (int t = 0; t < 8; t++) {
            int q = tid + t * 128, r = q >> 3, ch = q & 7;
            uint32_t so = SW((uint32_t)(r * 128 + ch * 16));
            size_t go = (size_t)r * E_DIM + k0 + ch * 8;
            cpa16(base + so,         A + go);
            cpa16(base + 16384 + so, B + go);
        }
        CP_COMMIT();
    };

    load(0);
#pragma unroll 1
    for (int c = 0; c < 4; c++) {
        if (c < 3) { load(c + 1); CP_WAIT(1); } else { CP_WAIT(0); }
        __syncthreads();
        uint32_t aB = sb + (c & 1) * STAGE_BYTES;
        compute_chunk(aB, aB + 16384, aRow, bRow, acc);
        __syncthreads();
    }

    // Epilogue
    const int tq = lane >> 2, tr = lane & 3;
    const bool offdiag = (i != j);
    __half* Pb = g_P + (size_t)b * N_TOK * N_TOK;
    __half* T = (__half*)sbase;          // [128 cols][132 rows] transpose staging
    float cs[16];
#pragma unroll
    for (int k = 0; k < 16; k++) cs[k] = 0.f;

#pragma unroll
    for (int mi = 0; mi < 4; mi++)
#pragma unroll
        for (int rh = 0; rh < 2; rh++) {
            int r = mbase + mi * 16 + rh * 8 + tq;
            int row = row0 + r;
            float rs = 0.f;
#pragma unroll
            for (int ni = 0; ni < 8; ni++) {
                float e0 = __expf(acc[mi][ni][rh * 2 + 0]);
                float e1 = __expf(acc[mi][ni][rh * 2 + 1]);
                rs += e0 + e1;
                int cc = nbase + ni * 8 + tr * 2;
                __half2 hv = __floats2half2_rn(e0, e1);
                *(uint32_t*)(Pb + (size_t)row * N_TOK + col0 + cc) = *(uint32_t*)&hv;
                if (offdiag) {
                    T[(cc + 0) * 132 + r] = __low2half(hv);
                    T[(cc + 1) * 132 + r] = __high2half(hv);
                    cs[ni * 2 + 0] += e0;
                    cs[ni * 2 + 1] += e1;
                }
            }
            rs += __shfl_xor_sync(0xffffffffu, rs, 1);
            rs += __shfl_xor_sync(0xffffffffu, rs, 2);
            if (tr == 0) atomicAdd(&g_rowsum[b * N_TOK + row], rs);
        }

    if (offdiag) {
        // column sums -> rowsum for mirrored rows
#pragma unroll
        for (int k = 0; k < 16; k++) {
            cs[k] += __shfl_xor_sync(0xffffffffu, cs[k], 4);
            cs[k] += __shfl_xor_sync(0xffffffffu, cs[k], 8);
            cs[k] += __shfl_xor_sync(0xffffffffu, cs[k], 16);
        }
        if (tq == 0) {
#pragma unroll
            for (int ni = 0; ni < 8; ni++) {
                int cc = nbase + ni * 8 + tr * 2;
                atomicAdd(&g_rowsum[b * N_TOK + col0 + cc + 0], cs[ni * 2 + 0]);
                atomicAdd(&g_rowsum[b * N_TOK + col0 + cc + 1], cs[ni * 2 + 1]);
            }
        }
        __syncthreads();
        // coalesced write of transposed block
#pragma unroll
        for (int t = 0; t < 64; t++) {
            int q = tid + t * 128;
            int cc = q >> 6, hp = q & 63;
            uint32_t val = *(uint32_t*)&T[cc * 132 + 2 * hp];
            *(uint32_t*)(Pb + (size_t)(col0 + cc) * N_TOK + row0 + 2 * hp) = val;
        }
    }
}

// ---------------------------------------------------------------------------
// Kernel 3: PV, 4 warps (2x2 of 64x64), 3 CTAs/SM. out = (P . h^T)/rowsum.
// ---------------------------------------------------------------------------
__global__ __launch_bounds__(128, 3) void k_pv(float* __restrict__ out) {
    extern __shared__ char smem_raw[];
    uint32_t sb0 = smem_u32(smem_raw);
    uint32_t sb = (sb0 + 1023) & ~1023u;
    char* sbase = smem_raw + (sb - sb0);
    const int tid = threadIdx.x, lane = tid & 31, w = tid >> 5;
    const int b = blockIdx.z, row0 = blockIdx.y * 128, col0 = blockIdx.x * 128;

    const __half* A  = g_P   + ((size_t)b * N_TOK + row0) * N_TOK;
    const __half* Bh = g_hth + ((size_t)b * H_DIM + col0) * N_TOK;

    const int mbase = (w & 1) * 64, nbase = (w >> 1) * 64;
    const uint32_t aRow = a_row_off(mbase, lane);
    const uint32_t bRow = b_row_off(nbase, lane);
    float acc[4][8][4] = {};

    auto load = [&](int c) {
        uint32_t base = sb + (c & 1) * STAGE_BYTES;
        int k0 = c * 64;
#pragma unroll
        for (int t = 0; t < 8; t++) {
            int q = tid + t * 128, r = q >> 3, ch = q & 7;
            uint32_t so = SW((uint32_t)(r * 128 + ch * 16));
            size_t go = (size_t)r * N_TOK + k0 + ch * 8;
            cpa16(base + so,         A + go);
            cpa16(base + 16384 + so, Bh + go);
        }
        CP_COMMIT();
    };

    load(0);
#pragma unroll 1
    for (int c = 0; c < 32; c++) {
        if (c < 31) { load(c + 1); CP_WAIT(1); } else { CP_WAIT(0); }
        __syncthreads();
        uint32_t aB = sb + (c & 1) * STAGE_BYTES;
        compute_chunk(aB, aB + 16384, aRow, bRow, acc);
        __syncthreads();
    }

    // Epilogue: scale by 1/rowsum, store, global sumsq.
    const int tq = lane >> 2, tr = lane & 3;
    float ssq = 0.f;
#pragma unroll
    for (int mi = 0; mi < 4; mi++)
#pragma unroll
        for (int rh = 0; rh < 2; rh++) {
            int row = row0 + mbase + mi * 16 + rh * 8 + tq;
            float inv = 1.f / g_rowsum[b * N_TOK + row];
#pragma unroll
            for (int ni = 0; ni < 8; ni++) {
                float v0 = acc[mi][ni][rh * 2 + 0] * inv;
                float v1 = acc[mi][ni][rh * 2 + 1] * inv;
                ssq = fmaf(v0, v0, fmaf(v1, v1, ssq));
                *(float2*)(out + ((size_t)row * B_SZ + b) * H_DIM
                               + col0 + nbase + ni * 8 + tr * 2) = make_float2(v0, v1);
            }
        }
#pragma unroll
    for (int o = 16; o; o >>= 1) ssq += __shfl_xor_sync(0xffffffffu, ssq, o);
    float* red = (float*)sbase;
    __syncthreads();
    if (lane == 0) red[w] = ssq;
    __syncthreads();
    if (tid == 0) atomicAdd(&g_sumsq[0], red[0] + red[1] + red[2] + red[3]);
}

// ---------------------------------------------------------------------------
// Kernel 4: out *= rsqrt(sum(out^2))
// ---------------------------------------------------------------------------
__global__ void k_scale(float* __restrict__ out) {
    float s = rsqrtf(g_sumsq[0]);
    const int total4 = (N_TOK * B_SZ * H_DIM) / 4;
    float4* o4 = (float4*)out;
    for (int i = blockIdx.x * blockDim.x + threadIdx.x; i < total4;
         i += gridDim.x * blockDim.x) {
        float4 v = o4[i];
        v.x *= s; v.y *= s; v.z *= s; v.w *= s;
        o4[i] = v;
    }
}

extern "C" void kernel_launch(void* const* d_in, const int* in_sizes, int n_in,
                              void* d_out, int out_size) {
    (void)in_sizes; (void)n_in; (void)out_size;
    const float* x = (const float*)d_in[0];
    const float* h = (const float*)d_in[1];
    float* out = (float*)d_out;

    cudaFuncSetAttribute(k_qk, cudaFuncAttributeMaxDynamicSharedMemorySize, GEMM_SMEM);
    cudaFuncSetAttribute(k_pv, cudaFuncAttributeMaxDynamicSharedMemorySize, GEMM_SMEM);

    k_normalize<<<(B_SZ * N_TOK) / 8, 256>>>(x);
    k_ht<<<dim3(N_TOK / 32, H_DIM / 32, B_SZ), dim3(32, 8)>>>(h);
    k_qk<<<dim3(136, 1, B_SZ), 128, GEMM_SMEM>>>();
    k_pv<<<dim3(4, 16, B_SZ), 128, GEMM_SMEM>>>(out);
    k_scale<<<1024, 256>>>(out);
}

// round 16
// speedup vs baseline: 1.0313x; 1.0313x over previous
#include <cuda_runtime.h>
#include <cuda_fp16.h>
#include <cstdint>

#define N_TOK 2048
#define B_SZ  8
#define E_DIM 256
#define H_DIM 512

// ---------------------------------------------------------------------------
// Scratch (static device globals — no runtime allocation).
// ---------------------------------------------------------------------------
__device__ __half g_x[(size_t)B_SZ * N_TOK * E_DIM];    // xn fp16 (B,N,E)
__device__ __half g_hth[(size_t)B_SZ * H_DIM * N_TOK];  // h^T fp16 (B,H,N)
__device__ __half g_P[(size_t)B_SZ * N_TOK * N_TOK];    // exp(scores) fp16
__device__ float g_rowsum[B_SZ * N_TOK];
__device__ float g_sumsq[1];

// ---------------------------------------------------------------------------
// Helpers (plain sm_103-compatible PTX: ldmatrix / mma.sync / cp.async)
// ---------------------------------------------------------------------------
__device__ __forceinline__ uint32_t smem_u32(const void* p) {
    uint32_t a;
    asm("{ .reg .u64 t; cvta.to.shared.u64 t, %1; cvt.u32.u64 %0, t; }" : "=r"(a) : "l"(p));
    return a;
}
__device__ __forceinline__ void cpa16(uint32_t dst, const void* src) {
    asm volatile("cp.async.cg.shared.global [%0], [%1], 16;"
                 :: "r"(dst), "l"(__cvta_generic_to_global(src)));
}
#define CP_COMMIT() asm volatile("cp.async.commit_group;" ::: "memory")
#define CP_WAIT(n)  asm volatile("cp.async.wait_group %0;" :: "n"(n) : "memory")

#define LDSM4(r0, r1, r2, r3, addr) \
    asm volatile("ldmatrix.sync.aligned.m8n8.x4.shared.b16 {%0,%1,%2,%3}, [%4];" \
                 : "=r"(r0), "=r"(r1), "=r"(r2), "=r"(r3) : "r"(addr))

#define MMA(c, a, b0, b1) \
    asm volatile("mma.sync.aligned.m16n8k16.row.col.f32.f16.f16.f32 " \
                 "{%0,%1,%2,%3},{%4,%5,%6,%7},{%8,%9},{%0,%1,%2,%3};" \
                 : "+f"((c)[0]), "+f"((c)[1]), "+f"((c)[2]), "+f"((c)[3]) \
                 : "r"((a)[0]), "r"((a)[1]), "r"((a)[2]), "r"((a)[3]), "r"(b0), "r"(b1))

// SW128 swizzle: 128-byte rows, xor bits[6:4] ^= bits[9:7]
#define SW(o) ((o) ^ (((o) >> 3) & 0x70u))

// per-lane ldmatrix row offsets (128-byte tile rows)
__device__ __forceinline__ uint32_t a_row_off(int mbase, int lane) {
    int row = mbase + (lane & 7) + ((lane >> 3) & 1) * 8;
    return (uint32_t)(row * 128 + (lane >> 4) * 16);
}
__device__ __forceinline__ uint32_t b_row_off(int nbase, int lane) {
    int row = nbase + (lane & 7) + ((lane >> 4) << 3);
    return (uint32_t)(row * 128 + ((lane >> 3) & 1) * 16);
}

#define STAGE_BYTES 32768
#define GEMM_SMEM (1024 + 3 * STAGE_BYTES)

// ---------------------------------------------------------------------------
// Kernel 1: row-normalize x (N,B,E) -> fp16 (B,N,E); zero accumulators.
// ---------------------------------------------------------------------------
__global__ __launch_bounds__(256) void k_normalize(const float* __restrict__ x) {
    if (blockIdx.x == 0) {
        for (int i = threadIdx.x; i < B_SZ * N_TOK; i += blockDim.x) g_rowsum[i] = 0.f;
        if (threadIdx.x == 0) g_sumsq[0] = 0.f;
    }
    int warp = (blockIdx.x * blockDim.x + threadIdx.x) >> 5;
    int lane = threadIdx.x & 31;
    if (warp >= B_SZ * N_TOK) return;
    int b = warp / N_TOK, i = warp % N_TOK;

    const float4* row = (const float4*)(x + ((size_t)i * B_SZ + b) * E_DIM);
    float4 v0 = row[lane], v1 = row[lane + 32];
    float ss = v0.x*v0.x + v0.y*v0.y + v0.z*v0.z + v0.w*v0.w
             + v1.x*v1.x + v1.y*v1.y + v1.z*v1.z + v1.w*v1.w;
#pragma unroll
    for (int o = 16; o; o >>= 1) ss += __shfl_xor_sync(0xffffffffu, ss, o);
    float r = rsqrtf(ss);

    size_t base = ((size_t)b * N_TOK + i) * E_DIM;
    float v[8] = {v0.x*r, v0.y*r, v0.z*r, v0.w*r, v1.x*r, v1.y*r, v1.z*r, v1.w*r};
#pragma unroll
    for (int half = 0; half < 2; half++) {
        int col = half * 128 + lane * 4;
        union { __half h4[4]; uint2 u; } uu;
#pragma unroll
        for (int k = 0; k < 4; k++) uu.h4[k] = __float2half_rn(v[half*4+k]);
        *(uint2*)(g_x + base + col) = uu.u;
    }
}

// ---------------------------------------------------------------------------
// Kernel 1b: transpose h (N,B,H) -> (B,H,N) fp16.
// ---------------------------------------------------------------------------
__global__ void k_ht(const float* __restrict__ h) {
    __shared__ float t[32][33];
    int b = blockIdx.z, tok0 = blockIdx.x * 32, hc0 = blockIdx.y * 32;
    int tx = threadIdx.x, ty = threadIdx.y;
#pragma unroll
    for (int k = 0; k < 4; k++)
        t[ty + 8*k][tx] = h[(size_t)(tok0 + ty + 8*k) * (B_SZ*H_DIM) + b*H_DIM + hc0 + tx];
    __syncthreads();
#pragma unroll
    for (int k = 0; k < 4; k++) {
        int r = ty + 8*k;
        g_hth[((size_t)b * H_DIM + hc0 + r) * N_TOK + tok0 + tx] = __float2half_rn(t[tx][r]);
    }
}

// ---------------------------------------------------------------------------
// Kernel 2: QK, symmetric, 8 warps of 32x64. Lower-triangle 128x128 blocks.
// 3-stage ring, single barrier per chunk.
// ---------------------------------------------------------------------------
__global__ __launch_bounds__(256, 2) void k_qk() {
    extern __shared__ char smem_raw[];
    uint32_t sbr = smem_u32(smem_raw);
    uint32_t sb = (sbr + 1023) & ~1023u;
    char* sbase = smem_raw + (sb - sbr);
    const int tid = threadIdx.x, lane = tid & 31, w = tid >> 5;
    const int b = blockIdx.z;

    // decode lower-triangle block (i, j), j <= i
    int bx = blockIdx.x;
    int i = (int)((sqrtf(8.0f * bx + 1.0f) - 1.0f) * 0.5f);
    while ((i + 1) * (i + 2) / 2 <= bx) i++;
    while (i * (i + 1) / 2 > bx) i--;
    int j = bx - i * (i + 1) / 2;
    const int row0 = i * 128, col0 = j * 128;

    const __half* A = g_x + ((size_t)b * N_TOK + row0) * E_DIM;
    const __half* B = g_x + ((size_t)b * N_TOK + col0) * E_DIM;

    const int mbase = (w & 3) * 32, nbase = (w >> 2) * 64;
    const uint32_t aRow = a_row_off(mbase, lane);
    const uint32_t bRow = b_row_off(nbase, lane);
    float acc[2][8][4] = {};

    auto load = [&](int c) {
        uint32_t base = sb + (c % 3) * STAGE_BYTES;
        int k0 = c * 64;
#pragma unroll
        for (int t = 0; t < 4; t++) {
            int q = tid + t * 256, r = q >> 3, ch = q & 7;
            uint32_t so = SW((uint32_t)(r * 128 + ch * 16));
            size_t go = (size_t)r * E_DIM + k0 + ch * 8;
            cpa16(base + so,         A + go);
            cpa16(base + 16384 + so, B + go);
        }
        CP_COMMIT();
    };

    load(0); load(1);
#pragma unroll 1
    for (int c = 0; c < 4; c++) {
        if (c < 3) { CP_WAIT(1); } else { CP_WAIT(0); }
        __syncthreads();              // all warps done with stage (c-1)%3 == (c+2)%3
        if (c + 2 < 4) load(c + 2);   // safe: overwrites stage (c+2)%3
        uint32_t aB = sb + (c % 3) * STAGE_BYTES, bB = aB + 16384;
#pragma unroll
        for (int k16 = 0; k16 < 4; k16++) {
            uint32_t aoff = SW(aRow + k16 * 32);
            uint32_t boff = SW(bRow + k16 * 32);
            uint32_t af[2][4], bf[4][4];
#pragma unroll
            for (int mi = 0; mi < 2; mi++)
                LDSM4(af[mi][0], af[mi][1], af[mi][2], af[mi][3], aB + aoff + mi * 2048);
#pragma unroll
            for (int g = 0; g < 4; g++)
                LDSM4(bf[g][0], bf[g][1], bf[g][2], bf[g][3], bB + boff + g * 2048);
#pragma unroll
            for (int mi = 0; mi < 2; mi++)
#pragma unroll
                for (int ni = 0; ni < 8; ni++) {
                    const int g = ni >> 1, p = (ni & 1) * 2;
                    MMA(acc[mi][ni], af[mi], bf[g][p], bf[g][p + 1]);
                }
        }
    }
    __syncthreads();   // protect SMEM reuse (transpose staging) below

    // Epilogue
    const int tq = lane >> 2, tr = lane & 3;
    const bool offdiag = (i != j);
    __half* Pb = g_P + (size_t)b * N_TOK * N_TOK;
    __half* T = (__half*)sbase;          // [128 cols][132 rows] transpose staging
    float cs[16];
#pragma unroll
    for (int k = 0; k < 16; k++) cs[k] = 0.f;

#pragma unroll
    for (int mi = 0; mi < 2; mi++)
#pragma unroll
        for (int rh = 0; rh < 2; rh++) {
            int r = mbase + mi * 16 + rh * 8 + tq;
            int row = row0 + r;
            float rs = 0.f;
#pragma unroll
            for (int ni = 0; ni < 8; ni++) {
                float e0 = __expf(acc[mi][ni][rh * 2 + 0]);
                float e1 = __expf(acc[mi][ni][rh * 2 + 1]);
                rs += e0 + e1;
                int cc = nbase + ni * 8 + tr * 2;
                __half2 hv = __floats2half2_rn(e0, e1);
                *(uint32_t*)(Pb + (size_t)row * N_TOK + col0 + cc) = *(uint32_t*)&hv;
                if (offdiag) {
                    T[(cc + 0) * 132 + r] = __low2half(hv);
                    T[(cc + 1) * 132 + r] = __high2half(hv);
                    cs[ni * 2 + 0] += e0;
                    cs[ni * 2 + 1] += e1;
                }
            }
            rs += __shfl_xor_sync(0xffffffffu, rs, 1);
            rs += __shfl_xor_sync(0xffffffffu, rs, 2);
            if (tr == 0) atomicAdd(&g_rowsum[b * N_TOK + row], rs);
        }

    if (offdiag) {
        // column sums -> rowsum for mirrored rows
#pragma unroll
        for (int k = 0; k < 16; k++) {
            cs[k] += __shfl_xor_sync(0xffffffffu, cs[k], 4);
            cs[k] += __shfl_xor_sync(0xffffffffu, cs[k], 8);
            cs[k] += __shfl_xor_sync(0xffffffffu, cs[k], 16);
        }
        if (tq == 0) {
#pragma unroll
            for (int ni = 0; ni < 8; ni++) {
                int cc = nbase + ni * 8 + tr * 2;
                atomicAdd(&g_rowsum[b * N_TOK + col0 + cc + 0], cs[ni * 2 + 0]);
                atomicAdd(&g_rowsum[b * N_TOK + col0 + cc + 1], cs[ni * 2 + 1]);
            }
        }
        __syncthreads();
        // coalesced write of transposed block
#pragma unroll
        for (int t = 0; t < 32; t++) {
            int q = tid + t * 256;
            int cc = q >> 6, hp = q & 63;
            uint32_t val = *(uint32_t*)&T[cc * 132 + 2 * hp];
            *(uint32_t*)(Pb + (size_t)(col0 + cc) * N_TOK + row0 + 2 * hp) = val;
        }
    }
}

// ---------------------------------------------------------------------------
// Kernel 3: PV (8 warps of 32x64, 2 CTAs/SM). 3-stage ring, single barrier
// per chunk. out = (P . h^T)/rowsum; global sumsq.
// ---------------------------------------------------------------------------
__global__ __launch_bounds__(256, 2) void k_pv(float* __restrict__ out) {
    extern __shared__ char smem_raw[];
    uint32_t sbr = smem_u32(smem_raw);
    uint32_t sb = (sbr + 1023) & ~1023u;
    char* sbase = smem_raw + (sb - sbr);
    const int tid = threadIdx.x, lane = tid & 31, w = tid >> 5;
    const int b = blockIdx.z, row0 = blockIdx.y * 128, col0 = blockIdx.x * 128;

    const __half* A  = g_P   + ((size_t)b * N_TOK + row0) * N_TOK;
    const __half* Bh = g_hth + ((size_t)b * H_DIM + col0) * N_TOK;

    const int mbase = (w & 3) * 32, nbase = (w >> 2) * 64;
    const uint32_t aRow = a_row_off(mbase, lane);
    const uint32_t bRow = b_row_off(nbase, lane);
    float acc[2][8][4] = {};

    auto load = [&](int c) {
        uint32_t base = sb + (c % 3) * STAGE_BYTES;
        int k0 = c * 64;
#pragma unroll
        for (int t = 0; t < 4; t++) {
            int q = tid + t * 256, r = q >> 3, ch = q & 7;
            uint32_t so = SW((uint32_t)(r * 128 + ch * 16));
            size_t go = (size_t)r * N_TOK + k0 + ch * 8;
            cpa16(base + so,         A + go);
            cpa16(base + 16384 + so, Bh + go);
        }
        CP_COMMIT();
    };

    load(0); load(1);
#pragma unroll 1
    for (int c = 0; c < 32; c++) {
        if (c < 31) { CP_WAIT(1); } else { CP_WAIT(0); }
        __syncthreads();               // all warps done with stage (c-1)%3 == (c+2)%3
        if (c + 2 < 32) load(c + 2);   // safe: overwrites stage (c+2)%3
        uint32_t aB = sb + (c % 3) * STAGE_BYTES, bB = aB + 16384;
#pragma unroll
        for (int k16 = 0; k16 < 4; k16++) {
            uint32_t aoff = SW(aRow + k16 * 32);
            uint32_t boff = SW(bRow + k16 * 32);
            uint32_t af[2][4], bf[4][4];
#pragma unroll
            for (int mi = 0; mi < 2; mi++)
                LDSM4(af[mi][0], af[mi][1], af[mi][2], af[mi][3], aB + aoff + mi * 2048);
#pragma unroll
            for (int g = 0; g < 4; g++)
                LDSM4(bf[g][0], bf[g][1], bf[g][2], bf[g][3], bB + boff + g * 2048);
#pragma unroll
            for (int mi = 0; mi < 2; mi++)
#pragma unroll
                for (int ni = 0; ni < 8; ni++) {
                    const int g = ni >> 1, p = (ni & 1) * 2;
                    MMA(acc[mi][ni], af[mi], bf[g][p], bf[g][p + 1]);
                }
        }
    }

    // Epilogue: scale by 1/rowsum, store, global sumsq.
    const int tq = lane >> 2, tr = lane & 3;
    float ssq = 0.f;
#pragma unroll
    for (int mi = 0; mi < 2; mi++)
#pragma unroll
        for (int rh = 0; rh < 2; rh++) {
            int row = row0 + mbase + mi * 16 + rh * 8 + tq;
            float inv = 1.f / g_rowsum[b * N_TOK + row];
#pragma unroll
            for (int ni = 0; ni < 8; ni++) {
                float v0 = acc[mi][ni][rh * 2 + 0] * inv;
                float v1 = acc[mi][ni][rh * 2 + 1] * inv;
                ssq = fmaf(v0, v0, fmaf(v1, v1, ssq));
                *(float2*)(out + ((size_t)row * B_SZ + b) * H_DIM
                               + col0 + nbase + ni * 8 + tr * 2) = make_float2(v0, v1);
            }
        }
#pragma unroll
    for (int o = 16; o; o >>= 1) ssq += __shfl_xor_sync(0xffffffffu, ssq, o);
    float* red = (float*)sbase;
    __syncthreads();                   // protect SMEM reuse below
    if (lane == 0) red[w] = ssq;
    __syncthreads();
    if (tid == 0) {
        float s = 0.f;
#pragma unroll
        for (int i = 0; i < 8; i++) s += red[i];
        atomicAdd(&g_sumsq[0], s);
    }
}

// ---------------------------------------------------------------------------
// Kernel 4: out *= rsqrt(sum(out^2))
// ---------------------------------------------------------------------------
__global__ void k_scale(float* __restrict__ out) {
    float s = rsqrtf(g_sumsq[0]);
    const int total4 = (N_TOK * B_SZ * H_DIM) / 4;
    float4* o4 = (float4*)out;
    for (int i = blockIdx.x * blockDim.x + threadIdx.x; i < total4;
         i += gridDim.x * blockDim.x) {
        float4 v = o4[i];
        v.x *= s; v.y *= s; v.z *= s; v.w *= s;
        o4[i] = v;
    }
}

extern "C" void kernel_launch(void* const* d_in, const int* in_sizes, int n_in,
                              void* d_out, int out_size) {
    (void)in_sizes; (void)n_in; (void)out_size;
    const float* x = (const float*)d_in[0];
    const float* h = (const float*)d_in[1];
    float* out = (float*)d_out;

    cudaFuncSetAttribute(k_qk, cudaFuncAttributeMaxDynamicSharedMemorySize, GEMM_SMEM);
    cudaFuncSetAttribute(k_pv, cudaFuncAttributeMaxDynamicSharedMemorySize, GEMM_SMEM);

    k_normalize<<<(B_SZ * N_TOK) / 8, 256>>>(x);
    k_ht<<<dim3(N_TOK / 32, H_DIM / 32, B_SZ), dim3(32, 8)>>>(h);
    k_qk<<<dim3(136, 1, B_SZ), 256, GEMM_SMEM>>>();
    k_pv<<<dim3(4, 16, B_SZ), 256, GEMM_SMEM>>>(out);
    k_scale<<<1024, 256>>>(out);
}